// round 11
// baseline (speedup 1.0000x reference)
#include <cuda_runtime.h>
#include <cuda_bf16.h>
#include <cuda_fp16.h>
#include <cstdint>

// Problem constants (fixed by the dataset)
#define NN_MAX   50000
#define EDGE_MAX 800000
#define IN_CH    256
#define C1       128
#define C2       64

// -------- scratch (no allocations allowed -> __device__ globals) -----------
__device__ int    g_deg     [NN_MAX];
__device__ int    g_prefix  [NN_MAX];
__device__ int    g_bsum    [256];
__device__ int    g_rowstart[NN_MAX];
__device__ int    g_cursor  [NN_MAX];
__device__ int2   g_csr2    [EDGE_MAX];      // (src, dis[src] bits) grouped by dst
__device__ float  g_dis     [NN_MAX];
__device__ __half g_h1      [NN_MAX * C1];   // x@W1 (raw, fp16)
__device__ float  g_x2      [NN_MAX * C1];   // relu output of layer 1 (fp32)
__device__ __half g_h2      [NN_MAX * C2];   // x2@W2 (raw, fp16)
// Pre-swizzled (SW128) bf16 hi/lo images of W^T, layout [kchunk][n][k64], 128B rows.
__device__ uint4 g_W1hi[4096], g_W1lo[4096];   // 4 chunks x 128n x 128B
__device__ uint4 g_W2hi[1024], g_W2lo[1024];   // 2 chunks x  64n x 128B

#define SW128(o) ((o) ^ (((o) >> 3) & 0x70))

__device__ __forceinline__ uint32_t smem_u32(const void* p) {
    uint32_t a;
    asm("{ .reg .u64 t; cvta.to.shared.u64 t, %1; cvt.u32.u64 %0, t; }" : "=r"(a) : "l"(p));
    return a;
}
__device__ __forceinline__ void ldsm_x4(uint32_t* r, uint32_t addr) {
    asm volatile("ldmatrix.sync.aligned.m8n8.x4.shared.b16 {%0,%1,%2,%3}, [%4];"
                 : "=r"(r[0]), "=r"(r[1]), "=r"(r[2]), "=r"(r[3]) : "r"(addr));
}
__device__ __forceinline__ void mma_bf16(float* d, const uint32_t* a,
                                         uint32_t b0, uint32_t b1) {
    asm volatile(
        "mma.sync.aligned.m16n8k16.row.col.f32.bf16.bf16.f32 "
        "{%0,%1,%2,%3}, {%4,%5,%6,%7}, {%8,%9}, {%0,%1,%2,%3};"
        : "+f"(d[0]), "+f"(d[1]), "+f"(d[2]), "+f"(d[3])
        : "r"(a[0]), "r"(a[1]), "r"(a[2]), "r"(a[3]), "r"(b0), "r"(b1));
}

// ---------------------------------------------------------------------------
// W-image prep only (main stream; overlapped with the side CSR chain).
__global__ void wprep_kernel(const float* __restrict__ W1, const float* __restrict__ W2) {
    int idx = blockIdx.x * blockDim.x + threadIdx.x;
    if (idx < IN_CH * C1) {
        int k = idx / C1, nn = idx % C1;
        float v = W1[k * C1 + nn];
        __nv_bfloat16 h = __float2bfloat16_rn(v);
        __nv_bfloat16 l = __float2bfloat16_rn(v - __bfloat162float(h));
        int c = k >> 6, kk = k & 63;
        int off = c * 16384 + SW128(nn * 128 + kk * 2);
        *(__nv_bfloat16*)((char*)g_W1hi + off) = h;
        *(__nv_bfloat16*)((char*)g_W1lo + off) = l;
        if (idx < C1 * C2) {
            int k2 = idx / C2, n2 = idx % C2;
            float v2 = W2[k2 * C2 + n2];
            __nv_bfloat16 h2 = __float2bfloat16_rn(v2);
            __nv_bfloat16 l2 = __float2bfloat16_rn(v2 - __bfloat162float(h2));
            int c2 = k2 >> 6, kk2 = k2 & 63;
            int off2 = c2 * 8192 + SW128(n2 * 128 + kk2 * 2);
            *(__nv_bfloat16*)((char*)g_W2hi + off2) = h2;
            *(__nv_bfloat16*)((char*)g_W2lo + off2) = l2;
        }
    }
}

__global__ void zero_deg(int n) {
    int i = blockIdx.x * blockDim.x + threadIdx.x;
    if (i < n) g_deg[i] = 0;
}

// Degree count: 4 edges per thread (int4 load) for MLP.
__global__ void deg_kernel(const int* __restrict__ dst, int E) {
    int base = (blockIdx.x * blockDim.x + threadIdx.x) * 4;
    if (base + 3 < E) {
        int4 d = *(const int4*)&dst[base];
        atomicAdd(&g_deg[d.x], 1);
        atomicAdd(&g_deg[d.y], 1);
        atomicAdd(&g_deg[d.z], 1);
        atomicAdd(&g_deg[d.w], 1);
    } else {
        for (int e = base; e < E; e++) atomicAdd(&g_deg[dst[e]], 1);
    }
}

// Parallel scan phase A: per-block exclusive prefix + block sums.
__global__ __launch_bounds__(512) void scanA(int n) {
    __shared__ int s[512];
    int t = threadIdx.x;
    int i = blockIdx.x * 512 + t;
    int v = (i < n) ? g_deg[i] : 0;
    s[t] = v; __syncthreads();
    for (int off = 1; off < 512; off <<= 1) {
        int u = (t >= off) ? s[t - off] : 0;
        __syncthreads(); s[t] += u; __syncthreads();
    }
    if (i < n) g_prefix[i] = s[t] - v;
    if (t == 511) g_bsum[blockIdx.x] = s[511];
}
// Phase B+C fused: every block redundantly scans the <=256 block sums in smem.
__global__ __launch_bounds__(256) void scanC(int n, int nb) {
    __shared__ int sb_[256];
    int t = threadIdx.x;
    int v = (t < nb) ? g_bsum[t] : 0;
    sb_[t] = v; __syncthreads();
    for (int off = 1; off < 256; off <<= 1) {
        int u = (t >= off) ? sb_[t - off] : 0;
        __syncthreads(); sb_[t] += u; __syncthreads();
    }
    if (t < nb) sb_[t] -= v;
    __syncthreads();
    int i = blockIdx.x * 256 + t;
    if (i >= n) return;
    int base = sb_[i >> 9] + g_prefix[i];
    g_rowstart[i] = base;
    g_cursor[i]   = base;
    g_dis[i]      = rsqrtf((float)g_deg[i] + 1.0f);
}

// CSR fill: packs (src, dis[src]) per edge; 4 edges per thread for MLP.
__global__ void fill_csr(const int* __restrict__ src, const int* __restrict__ dst, int E) {
    int base = (blockIdx.x * blockDim.x + threadIdx.x) * 4;
    if (base + 3 < E) {
        int4 d = *(const int4*)&dst[base];
        int4 s = *(const int4*)&src[base];
        float f0 = g_dis[s.x], f1 = g_dis[s.y], f2 = g_dis[s.z], f3 = g_dis[s.w];
        int p0 = atomicAdd(&g_cursor[d.x], 1);
        int p1 = atomicAdd(&g_cursor[d.y], 1);
        int p2 = atomicAdd(&g_cursor[d.z], 1);
        int p3 = atomicAdd(&g_cursor[d.w], 1);
        g_csr2[p0] = make_int2(s.x, __float_as_int(f0));
        g_csr2[p1] = make_int2(s.y, __float_as_int(f1));
        g_csr2[p2] = make_int2(s.z, __float_as_int(f2));
        g_csr2[p3] = make_int2(s.w, __float_as_int(f3));
    } else {
        for (int e = base; e < E; e++) {
            int s = src[e];
            int p = atomicAdd(&g_cursor[dst[e]], 1);
            g_csr2[p] = make_int2(s, __float_as_int(g_dis[s]));
        }
    }
}

// ---------------------------------------------------------------------------
// Warp-MMA split-bf16 GEMM: h[m][n] = half( sum_k A[m][k] * W[k][n] )
// m_base: first row handled by block 0 (for half-split launches).
template<int MTILE, int NDIM, int KDIM, int WM, int WN>
__global__ __launch_bounds__(256) void gemm_mma(
    const float* __restrict__ A, const uint4* __restrict__ Bhi,
    const uint4* __restrict__ Blo, __half* __restrict__ Cout, int M, int m_base)
{
    constexpr int SA_HI = 0;
    constexpr int SA_LO = MTILE * 128;
    constexpr int SB_HI = 2 * MTILE * 128;
    constexpr int SB_LO = SB_HI + NDIM * 128;
    constexpr int NCH   = KDIM / 64;
    constexpr int BNV   = NDIM * 8;

    extern __shared__ char smem[];
    const uint32_t sb = smem_u32(smem);
    const int tid  = threadIdx.x;
    const int wid  = tid >> 5, lane = tid & 31;
    const int wm   = wid / WN, wn = wid % WN;
    const int m0   = m_base + blockIdx.x * MTILE;

    const int row_l  = lane & 15;
    const int colsel = (lane >> 4) * 8;

    float acc[2][NDIM / 8][4];
#pragma unroll
    for (int i = 0; i < 2; i++)
#pragma unroll
        for (int j = 0; j < NDIM / 8; j++)
#pragma unroll
            for (int q = 0; q < 4; q++) acc[i][j][q] = 0.0f;

    for (int c = 0; c < NCH; c++) {
        for (int i = tid; i < MTILE * 16; i += 256) {
            int m = i >> 4, kk = (i & 15) * 4;
            int gm = m0 + m;
            float4 v = make_float4(0.f, 0.f, 0.f, 0.f);
            if (gm < M) v = *(const float4*)&A[(size_t)gm * KDIM + c * 64 + kk];
            __nv_bfloat16 h0 = __float2bfloat16_rn(v.x), h1 = __float2bfloat16_rn(v.y);
            __nv_bfloat16 h2 = __float2bfloat16_rn(v.z), h3 = __float2bfloat16_rn(v.w);
            __nv_bfloat16 l0 = __float2bfloat16_rn(v.x - __bfloat162float(h0));
            __nv_bfloat16 l1 = __float2bfloat16_rn(v.y - __bfloat162float(h1));
            __nv_bfloat16 l2 = __float2bfloat16_rn(v.z - __bfloat162float(h2));
            __nv_bfloat16 l3 = __float2bfloat16_rn(v.w - __bfloat162float(h3));
            uint32_t hA = ((uint32_t)__bfloat16_as_ushort(h1) << 16) | __bfloat16_as_ushort(h0);
            uint32_t hB = ((uint32_t)__bfloat16_as_ushort(h3) << 16) | __bfloat16_as_ushort(h2);
            uint32_t lA = ((uint32_t)__bfloat16_as_ushort(l1) << 16) | __bfloat16_as_ushort(l0);
            uint32_t lB = ((uint32_t)__bfloat16_as_ushort(l3) << 16) | __bfloat16_as_ushort(l2);
            int off = SW128(m * 128 + kk * 2);
            *(uint2*)(smem + SA_HI + off) = make_uint2(hA, hB);
            *(uint2*)(smem + SA_LO + off) = make_uint2(lA, lB);
        }
        {
            uint4* bh = (uint4*)(smem + SB_HI);
            uint4* bl = (uint4*)(smem + SB_LO);
            const uint4* gh = Bhi + (size_t)c * BNV;
            const uint4* gl = Blo + (size_t)c * BNV;
            for (int i = tid; i < BNV; i += 256) { bh[i] = gh[i]; bl[i] = gl[i]; }
        }
        __syncthreads();

#pragma unroll
        for (int k16 = 0; k16 < 4; k16++) {
            const int kb = k16 * 16;
            uint32_t ah[2][4], al[2][4];
#pragma unroll
            for (int im = 0; im < 2; im++) {
                int aoff = SW128((wm * 32 + im * 16 + row_l) * 128 + (kb + colsel) * 2);
                ldsm_x4(ah[im], sb + SA_HI + aoff);
                ldsm_x4(al[im], sb + SA_LO + aoff);
            }
#pragma unroll
            for (int j2 = 0; j2 < NDIM / (WN * 16); j2++) {
                int boff = SW128((wn * 64 + j2 * 16 + row_l) * 128 + (kb + colsel) * 2);
                uint32_t bh[4], bl[4];
                ldsm_x4(bh, sb + SB_HI + boff);
                ldsm_x4(bl, sb + SB_LO + boff);
#pragma unroll
                for (int im = 0; im < 2; im++) {
                    float* d0 = acc[im][2 * j2];
                    float* d1 = acc[im][2 * j2 + 1];
                    mma_bf16(d0, ah[im], bh[0], bh[2]);
                    mma_bf16(d0, ah[im], bl[0], bl[2]);
                    mma_bf16(d0, al[im], bh[0], bh[2]);
                    mma_bf16(d1, ah[im], bh[1], bh[3]);
                    mma_bf16(d1, ah[im], bl[1], bl[3]);
                    mma_bf16(d1, al[im], bh[1], bh[3]);
                }
            }
        }
        __syncthreads();
    }

#pragma unroll
    for (int im = 0; im < 2; im++) {
        int row0 = m0 + wm * 32 + im * 16 + (lane >> 2);
        int row1 = row0 + 8;
#pragma unroll
        for (int j = 0; j < NDIM / (WN * 8); j++) {
            int col = wn * 64 + j * 8 + (lane & 3) * 2;
            if (row0 < M)
                *(__half2*)&Cout[(size_t)row0 * NDIM + col] =
                    __floats2half2_rn(acc[im][j][0], acc[im][j][1]);
            if (row1 < M)
                *(__half2*)&Cout[(size_t)row1 * NDIM + col] =
                    __floats2half2_rn(acc[im][j][2], acc[im][j][3]);
        }
    }
}

// ---------------------------------------------------------------------------
// Gather-reduce aggregation, 128 fp16 channels over node range [node0, node1).
__global__ __launch_bounds__(256)
void agg128(const __half* __restrict__ hs, const float* __restrict__ bias,
            float* __restrict__ out, int node0, int node1) {
    int warp = (blockIdx.x * blockDim.x + threadIdx.x) >> 5;
    int lane = threadIdx.x & 31;
    int node = node0 + warp;
    if (node >= node1) return;
    const float dnode = g_dis[node];

    float4 acc;
    {
        uint2 r = *(const uint2*)&hs[(size_t)node * C1 + lane * 4];
        float2 f0 = __half22float2(*(__half2*)&r.x);
        float2 f1 = __half22float2(*(__half2*)&r.y);
        acc = make_float4(f0.x * dnode, f0.y * dnode, f1.x * dnode, f1.y * dnode);
    }
    int e   = g_rowstart[node];
    int cnt = g_deg[node];

    while (cnt > 0) {
        int take = min(cnt, 32);
        int2 sd = make_int2(0, 0);
        if (lane < take) sd = g_csr2[e + lane];
        int k = 0;
        for (; k + 8 <= take; k += 8) {
            uint2 r[8]; float dq[8];
#pragma unroll
            for (int q = 0; q < 8; q++) {
                int sq = __shfl_sync(0xffffffffu, sd.x, k + q);
                dq[q]  = __int_as_float(__shfl_sync(0xffffffffu, sd.y, k + q));
                r[q] = *(const uint2*)&hs[(size_t)sq * C1 + lane * 4];
            }
#pragma unroll
            for (int q = 0; q < 8; q++) {
                float2 f0 = __half22float2(*(__half2*)&r[q].x);
                float2 f1 = __half22float2(*(__half2*)&r[q].y);
                acc.x = fmaf(f0.x, dq[q], acc.x);
                acc.y = fmaf(f0.y, dq[q], acc.y);
                acc.z = fmaf(f1.x, dq[q], acc.z);
                acc.w = fmaf(f1.y, dq[q], acc.w);
            }
        }
        for (; k < take; k++) {
            int sk = __shfl_sync(0xffffffffu, sd.x, k);
            float dk = __int_as_float(__shfl_sync(0xffffffffu, sd.y, k));
            uint2 r = *(const uint2*)&hs[(size_t)sk * C1 + lane * 4];
            float2 f0 = __half22float2(*(__half2*)&r.x);
            float2 f1 = __half22float2(*(__half2*)&r.y);
            acc.x = fmaf(f0.x, dk, acc.x);
            acc.y = fmaf(f0.y, dk, acc.y);
            acc.z = fmaf(f1.x, dk, acc.z);
            acc.w = fmaf(f1.y, dk, acc.w);
        }
        e += take; cnt -= take;
    }

    float4 bb = ((const float4*)bias)[lane];
    float4 r;
    r.x = fmaxf(fmaf(dnode, acc.x, bb.x), 0.0f);
    r.y = fmaxf(fmaf(dnode, acc.y, bb.y), 0.0f);
    r.z = fmaxf(fmaf(dnode, acc.z, bb.z), 0.0f);
    r.w = fmaxf(fmaf(dnode, acc.w, bb.w), 0.0f);
    *(float4*)&out[(size_t)node * C1 + lane * 4] = r;
}

// 64-ch fp16 aggregation: one warp per node, each lane owns 2 channels (half2).
__global__ __launch_bounds__(256)
void agg64(const __half* __restrict__ hs, const float* __restrict__ bias,
           float* __restrict__ out, int n) {
    int warp = (blockIdx.x * blockDim.x + threadIdx.x) >> 5;
    int lane = threadIdx.x & 31;
    if (warp >= n) return;
    const int node = warp;
    const float dnode = g_dis[node];

    float2 acc;
    {
        uint32_t r = *(const uint32_t*)&hs[(size_t)node * C2 + lane * 2];
        float2 f = __half22float2(*(__half2*)&r);
        acc = make_float2(f.x * dnode, f.y * dnode);
    }
    int e   = g_rowstart[node];
    int cnt = g_deg[node];

    while (cnt > 0) {
        int take = min(cnt, 32);
        int2 sd = make_int2(0, 0);
        if (lane < take) sd = g_csr2[e + lane];
        int k = 0;
        for (; k + 8 <= take; k += 8) {
            uint32_t r[8]; float dq[8];
#pragma unroll
            for (int q = 0; q < 8; q++) {
                int sq = __shfl_sync(0xffffffffu, sd.x, k + q);
                dq[q]  = __int_as_float(__shfl_sync(0xffffffffu, sd.y, k + q));
                r[q] = *(const uint32_t*)&hs[(size_t)sq * C2 + lane * 2];
            }
#pragma unroll
            for (int q = 0; q < 8; q++) {
                float2 f = __half22float2(*(__half2*)&r[q]);
                acc.x = fmaf(f.x, dq[q], acc.x);
                acc.y = fmaf(f.y, dq[q], acc.y);
            }
        }
        for (; k < take; k++) {
            int sk = __shfl_sync(0xffffffffu, sd.x, k);
            float dk = __int_as_float(__shfl_sync(0xffffffffu, sd.y, k));
            uint32_t r = *(const uint32_t*)&hs[(size_t)sk * C2 + lane * 2];
            float2 f = __half22float2(*(__half2*)&r);
            acc.x = fmaf(f.x, dk, acc.x);
            acc.y = fmaf(f.y, dk, acc.y);
        }
        e += take; cnt -= take;
    }

    float2 bb = ((const float2*)bias)[lane];
    float2 r;
    r.x = fmaxf(fmaf(dnode, acc.x, bb.x), 0.0f);
    r.y = fmaxf(fmaf(dnode, acc.y, bb.y), 0.0f);
    *(float2*)&out[(size_t)node * C2 + lane * 2] = r;
}

// ---------------------------------------------------------------------------
extern "C" void kernel_launch(void* const* d_in, const int* in_sizes, int n_in,
                              void* d_out, int out_size) {
    const float* x  = (const float*)d_in[0];
    const int*   ei = (const int*)d_in[1];
    const float* W1 = (const float*)d_in[2];
    const float* b1 = (const float*)d_in[3];
    const float* W2 = (const float*)d_in[4];
    const float* b2 = (const float*)d_in[5];
    float* out = (float*)d_out;

    const int E = in_sizes[1] / 2;
    const int N = in_sizes[0] / IN_CH;
    const int* src = ei;
    const int* dst = ei + E;

    __half *h1, *h2;
    float *x2;
    uint4 *w1h, *w1l, *w2h, *w2l;
    cudaGetSymbolAddress((void**)&h1,  g_h1);
    cudaGetSymbolAddress((void**)&x2,  g_x2);
    cudaGetSymbolAddress((void**)&h2,  g_h2);
    cudaGetSymbolAddress((void**)&w1h, g_W1hi);
    cudaGetSymbolAddress((void**)&w1l, g_W1lo);
    cudaGetSymbolAddress((void**)&w2h, g_W2hi);
    cudaGetSymbolAddress((void**)&w2l, g_W2lo);

    constexpr int SMEM1 = 2 * 128 * 128 + 2 * 128 * 128;  // 65536
    constexpr int SMEM2 = 2 * 256 * 128 + 2 * 64 * 128;   // 81920
    cudaFuncSetAttribute(gemm_mma<128, 128, 256, 4, 2>,
                         cudaFuncAttributeMaxDynamicSharedMemorySize, SMEM1);
    cudaFuncSetAttribute(gemm_mma<256, 64, 128, 8, 1>,
                         cudaFuncAttributeMaxDynamicSharedMemorySize, SMEM2);

    // Lazily-created side stream + events (first call is uncaptured).
    static cudaStream_t s_side = nullptr;
    static cudaEvent_t  ev_fork = nullptr, ev_chain = nullptr;
    static cudaEvent_t  ev_a0 = nullptr, ev_a1 = nullptr, ev_g2 = nullptr;
    if (!s_side) {
        cudaStreamCreateWithFlags(&s_side, cudaStreamNonBlocking);
        cudaEventCreateWithFlags(&ev_fork,  cudaEventDisableTiming);
        cudaEventCreateWithFlags(&ev_chain, cudaEventDisableTiming);
        cudaEventCreateWithFlags(&ev_a0,    cudaEventDisableTiming);
        cudaEventCreateWithFlags(&ev_a1,    cudaEventDisableTiming);
        cudaEventCreateWithFlags(&ev_g2,    cudaEventDisableTiming);
    }

    // Node split for agg128/gemm2 overlap (multiple of 256 for clean tiles).
    const int NH = ((N / 2 + 255) / 256) * 256;   // 25088 for N=50000

    // Fork immediately: side builds CSR chain, main builds W images + gemm1.
    cudaEventRecord(ev_fork, 0);
    cudaStreamWaitEvent(s_side, ev_fork, 0);

    // --- side: zero_deg -> deg -> scanA -> scanC -> fill_csr ---
    zero_deg<<<(N + 255) / 256, 256, 0, s_side>>>(N);
    deg_kernel<<<((E + 3) / 4 + 255) / 256, 256, 0, s_side>>>(dst, E);
    int nb = (N + 511) / 512;
    scanA<<<nb, 512, 0, s_side>>>(N);
    scanC<<<(N + 255) / 256, 256, 0, s_side>>>(N, nb);
    fill_csr<<<((E + 3) / 4 + 255) / 256, 256, 0, s_side>>>(src, dst, E);
    cudaEventRecord(ev_chain, s_side);

    // --- main: W images, then gemm1 (needs only W1 images + x) ---
    wprep_kernel<<<(IN_CH * C1 + 255) / 256, 256>>>(W1, W2);
    gemm_mma<128, 128, 256, 4, 2><<<(N + 127) / 128, 256, SMEM1>>>(x, w1h, w1l, h1, N, 0);

    // Join chain, then aggregate layer 1 in two halves.
    cudaStreamWaitEvent(0, ev_chain, 0);
    agg128<<<(NH * 32 + 255) / 256, 256>>>(h1, b1, x2, 0, NH);
    cudaEventRecord(ev_a0, 0);
    agg128<<<((N - NH) * 32 + 255) / 256, 256>>>(h1, b1, x2, NH, N);
    cudaEventRecord(ev_a1, 0);

    // --- side: gemm2 halves; h0 overlaps agg128_h1 on main ---
    cudaStreamWaitEvent(s_side, ev_a0, 0);
    gemm_mma<256, 64, 128, 8, 1><<<NH / 256, 256, SMEM2, s_side>>>(x2, w2h, w2l, h2, N, 0);
    cudaStreamWaitEvent(s_side, ev_a1, 0);
    gemm_mma<256, 64, 128, 8, 1><<<(N - NH + 255) / 256, 256, SMEM2, s_side>>>(x2, w2h, w2l, h2, N, NH);
    cudaEventRecord(ev_g2, s_side);

    // Final aggregation needs all of h2.
    cudaStreamWaitEvent(0, ev_g2, 0);
    agg64<<<(N * 32 + 255) / 256, 256>>>(h2, b2, out, N);
}

// round 12
// speedup vs baseline: 1.0965x; 1.0965x over previous
#include <cuda_runtime.h>
#include <cuda_bf16.h>
#include <cuda_fp16.h>
#include <cstdint>

// Problem constants (fixed by the dataset)
#define NN_MAX   50000
#define EDGE_MAX 800000
#define IN_CH    256
#define C1       128
#define C2       64

// -------- scratch (no allocations allowed -> __device__ globals) -----------
__device__ int    g_deg     [NN_MAX];
__device__ int    g_prefix  [NN_MAX];
__device__ int    g_bsum    [256];
__device__ int    g_rowstart[NN_MAX];
__device__ int    g_cursor  [NN_MAX];
__device__ int2   g_csr2    [EDGE_MAX];      // (src, dis[src] bits) grouped by dst
__device__ float  g_dis     [NN_MAX];
__device__ __half g_h1      [NN_MAX * C1];   // x@W1 (raw, fp16)
__device__ float  g_x2      [NN_MAX * C1];   // relu output of layer 1 (fp32)
__device__ __half g_h2      [NN_MAX * C2];   // x2@W2 (raw, fp16)
// Pre-swizzled (SW128) bf16 hi/lo images of W^T, layout [kchunk][n][k64], 128B rows.
__device__ uint4 g_W1hi[4096], g_W1lo[4096];   // 4 chunks x 128n x 128B
__device__ uint4 g_W2hi[1024], g_W2lo[1024];   // 2 chunks x  64n x 128B

#define SW128(o) ((o) ^ (((o) >> 3) & 0x70))

__device__ __forceinline__ uint32_t smem_u32(const void* p) {
    uint32_t a;
    asm("{ .reg .u64 t; cvta.to.shared.u64 t, %1; cvt.u32.u64 %0, t; }" : "=r"(a) : "l"(p));
    return a;
}
__device__ __forceinline__ void ldsm_x4(uint32_t* r, uint32_t addr) {
    asm volatile("ldmatrix.sync.aligned.m8n8.x4.shared.b16 {%0,%1,%2,%3}, [%4];"
                 : "=r"(r[0]), "=r"(r[1]), "=r"(r[2]), "=r"(r[3]) : "r"(addr));
}
__device__ __forceinline__ void mma_bf16(float* d, const uint32_t* a,
                                         uint32_t b0, uint32_t b1) {
    asm volatile(
        "mma.sync.aligned.m16n8k16.row.col.f32.bf16.bf16.f32 "
        "{%0,%1,%2,%3}, {%4,%5,%6,%7}, {%8,%9}, {%0,%1,%2,%3};"
        : "+f"(d[0]), "+f"(d[1]), "+f"(d[2]), "+f"(d[3])
        : "r"(a[0]), "r"(a[1]), "r"(a[2]), "r"(a[3]), "r"(b0), "r"(b1));
}

// ---------------------------------------------------------------------------
// W-image prep only (main stream; overlapped with the side CSR chain).
__global__ void wprep_kernel(const float* __restrict__ W1, const float* __restrict__ W2) {
    int idx = blockIdx.x * blockDim.x + threadIdx.x;
    if (idx < IN_CH * C1) {
        int k = idx / C1, nn = idx % C1;
        float v = W1[k * C1 + nn];
        __nv_bfloat16 h = __float2bfloat16_rn(v);
        __nv_bfloat16 l = __float2bfloat16_rn(v - __bfloat162float(h));
        int c = k >> 6, kk = k & 63;
        int off = c * 16384 + SW128(nn * 128 + kk * 2);
        *(__nv_bfloat16*)((char*)g_W1hi + off) = h;
        *(__nv_bfloat16*)((char*)g_W1lo + off) = l;
        if (idx < C1 * C2) {
            int k2 = idx / C2, n2 = idx % C2;
            float v2 = W2[k2 * C2 + n2];
            __nv_bfloat16 h2 = __float2bfloat16_rn(v2);
            __nv_bfloat16 l2 = __float2bfloat16_rn(v2 - __bfloat162float(h2));
            int c2 = k2 >> 6, kk2 = k2 & 63;
            int off2 = c2 * 8192 + SW128(n2 * 128 + kk2 * 2);
            *(__nv_bfloat16*)((char*)g_W2hi + off2) = h2;
            *(__nv_bfloat16*)((char*)g_W2lo + off2) = l2;
        }
    }
}

__global__ void zero_deg(int n) {
    int i = blockIdx.x * blockDim.x + threadIdx.x;
    if (i < n) g_deg[i] = 0;
}

// Degree count: 4 edges per thread (int4 load) for MLP.
__global__ void deg_kernel(const int* __restrict__ dst, int E) {
    int base = (blockIdx.x * blockDim.x + threadIdx.x) * 4;
    if (base + 3 < E) {
        int4 d = *(const int4*)&dst[base];
        atomicAdd(&g_deg[d.x], 1);
        atomicAdd(&g_deg[d.y], 1);
        atomicAdd(&g_deg[d.z], 1);
        atomicAdd(&g_deg[d.w], 1);
    } else {
        for (int e = base; e < E; e++) atomicAdd(&g_deg[dst[e]], 1);
    }
}

// Parallel scan phase A: per-block exclusive prefix + block sums.
__global__ __launch_bounds__(512) void scanA(int n) {
    __shared__ int s[512];
    int t = threadIdx.x;
    int i = blockIdx.x * 512 + t;
    int v = (i < n) ? g_deg[i] : 0;
    s[t] = v; __syncthreads();
    for (int off = 1; off < 512; off <<= 1) {
        int u = (t >= off) ? s[t - off] : 0;
        __syncthreads(); s[t] += u; __syncthreads();
    }
    if (i < n) g_prefix[i] = s[t] - v;
    if (t == 511) g_bsum[blockIdx.x] = s[511];
}
// Phase B+C fused: every block redundantly scans the <=256 block sums in smem.
__global__ __launch_bounds__(256) void scanC(int n, int nb) {
    __shared__ int sb_[256];
    int t = threadIdx.x;
    int v = (t < nb) ? g_bsum[t] : 0;
    sb_[t] = v; __syncthreads();
    for (int off = 1; off < 256; off <<= 1) {
        int u = (t >= off) ? sb_[t - off] : 0;
        __syncthreads(); sb_[t] += u; __syncthreads();
    }
    if (t < nb) sb_[t] -= v;
    __syncthreads();
    int i = blockIdx.x * 256 + t;
    if (i >= n) return;
    int base = sb_[i >> 9] + g_prefix[i];
    g_rowstart[i] = base;
    g_cursor[i]   = base;
    g_dis[i]      = rsqrtf((float)g_deg[i] + 1.0f);
}

// CSR fill: packs (src, dis[src]) per edge; 4 edges per thread for MLP.
__global__ void fill_csr(const int* __restrict__ src, const int* __restrict__ dst, int E) {
    int base = (blockIdx.x * blockDim.x + threadIdx.x) * 4;
    if (base + 3 < E) {
        int4 d = *(const int4*)&dst[base];
        int4 s = *(const int4*)&src[base];
        float f0 = g_dis[s.x], f1 = g_dis[s.y], f2 = g_dis[s.z], f3 = g_dis[s.w];
        int p0 = atomicAdd(&g_cursor[d.x], 1);
        int p1 = atomicAdd(&g_cursor[d.y], 1);
        int p2 = atomicAdd(&g_cursor[d.z], 1);
        int p3 = atomicAdd(&g_cursor[d.w], 1);
        g_csr2[p0] = make_int2(s.x, __float_as_int(f0));
        g_csr2[p1] = make_int2(s.y, __float_as_int(f1));
        g_csr2[p2] = make_int2(s.z, __float_as_int(f2));
        g_csr2[p3] = make_int2(s.w, __float_as_int(f3));
    } else {
        for (int e = base; e < E; e++) {
            int s = src[e];
            int p = atomicAdd(&g_cursor[dst[e]], 1);
            g_csr2[p] = make_int2(s, __float_as_int(g_dis[s]));
        }
    }
}

// ---------------------------------------------------------------------------
// Warp-MMA split-bf16 GEMM: h[m][n] = half( sum_k A[m][k] * W[k][n] )
template<int MTILE, int NDIM, int KDIM, int WM, int WN>
__global__ __launch_bounds__(256) void gemm_mma(
    const float* __restrict__ A, const uint4* __restrict__ Bhi,
    const uint4* __restrict__ Blo, __half* __restrict__ Cout, int M)
{
    constexpr int SA_HI = 0;
    constexpr int SA_LO = MTILE * 128;
    constexpr int SB_HI = 2 * MTILE * 128;
    constexpr int SB_LO = SB_HI + NDIM * 128;
    constexpr int NCH   = KDIM / 64;
    constexpr int BNV   = NDIM * 8;

    extern __shared__ char smem[];
    const uint32_t sb = smem_u32(smem);
    const int tid  = threadIdx.x;
    const int wid  = tid >> 5, lane = tid & 31;
    const int wm   = wid / WN, wn = wid % WN;
    const int m0   = blockIdx.x * MTILE;

    const int row_l  = lane & 15;
    const int colsel = (lane >> 4) * 8;

    float acc[2][NDIM / 8][4];
#pragma unroll
    for (int i = 0; i < 2; i++)
#pragma unroll
        for (int j = 0; j < NDIM / 8; j++)
#pragma unroll
            for (int q = 0; q < 4; q++) acc[i][j][q] = 0.0f;

    for (int c = 0; c < NCH; c++) {
        for (int i = tid; i < MTILE * 16; i += 256) {
            int m = i >> 4, kk = (i & 15) * 4;
            int gm = m0 + m;
            float4 v = make_float4(0.f, 0.f, 0.f, 0.f);
            if (gm < M) v = *(const float4*)&A[(size_t)gm * KDIM + c * 64 + kk];
            __nv_bfloat16 h0 = __float2bfloat16_rn(v.x), h1 = __float2bfloat16_rn(v.y);
            __nv_bfloat16 h2 = __float2bfloat16_rn(v.z), h3 = __float2bfloat16_rn(v.w);
            __nv_bfloat16 l0 = __float2bfloat16_rn(v.x - __bfloat162float(h0));
            __nv_bfloat16 l1 = __float2bfloat16_rn(v.y - __bfloat162float(h1));
            __nv_bfloat16 l2 = __float2bfloat16_rn(v.z - __bfloat162float(h2));
            __nv_bfloat16 l3 = __float2bfloat16_rn(v.w - __bfloat162float(h3));
            uint32_t hA = ((uint32_t)__bfloat16_as_ushort(h1) << 16) | __bfloat16_as_ushort(h0);
            uint32_t hB = ((uint32_t)__bfloat16_as_ushort(h3) << 16) | __bfloat16_as_ushort(h2);
            uint32_t lA = ((uint32_t)__bfloat16_as_ushort(l1) << 16) | __bfloat16_as_ushort(l0);
            uint32_t lB = ((uint32_t)__bfloat16_as_ushort(l3) << 16) | __bfloat16_as_ushort(l2);
            int off = SW128(m * 128 + kk * 2);
            *(uint2*)(smem + SA_HI + off) = make_uint2(hA, hB);
            *(uint2*)(smem + SA_LO + off) = make_uint2(lA, lB);
        }
        {
            uint4* bh = (uint4*)(smem + SB_HI);
            uint4* bl = (uint4*)(smem + SB_LO);
            const uint4* gh = Bhi + (size_t)c * BNV;
            const uint4* gl = Blo + (size_t)c * BNV;
            for (int i = tid; i < BNV; i += 256) { bh[i] = gh[i]; bl[i] = gl[i]; }
        }
        __syncthreads();

#pragma unroll
        for (int k16 = 0; k16 < 4; k16++) {
            const int kb = k16 * 16;
            uint32_t ah[2][4], al[2][4];
#pragma unroll
            for (int im = 0; im < 2; im++) {
                int aoff = SW128((wm * 32 + im * 16 + row_l) * 128 + (kb + colsel) * 2);
                ldsm_x4(ah[im], sb + SA_HI + aoff);
                ldsm_x4(al[im], sb + SA_LO + aoff);
            }
#pragma unroll
            for (int j2 = 0; j2 < NDIM / (WN * 16); j2++) {
                int boff = SW128((wn * 64 + j2 * 16 + row_l) * 128 + (kb + colsel) * 2);
                uint32_t bh[4], bl[4];
                ldsm_x4(bh, sb + SB_HI + boff);
                ldsm_x4(bl, sb + SB_LO + boff);
#pragma unroll
                for (int im = 0; im < 2; im++) {
                    float* d0 = acc[im][2 * j2];
                    float* d1 = acc[im][2 * j2 + 1];
                    mma_bf16(d0, ah[im], bh[0], bh[2]);
                    mma_bf16(d0, ah[im], bl[0], bl[2]);
                    mma_bf16(d0, al[im], bh[0], bh[2]);
                    mma_bf16(d1, ah[im], bh[1], bh[3]);
                    mma_bf16(d1, ah[im], bl[1], bl[3]);
                    mma_bf16(d1, al[im], bh[1], bh[3]);
                }
            }
        }
        __syncthreads();
    }

#pragma unroll
    for (int im = 0; im < 2; im++) {
        int row0 = m0 + wm * 32 + im * 16 + (lane >> 2);
        int row1 = row0 + 8;
#pragma unroll
        for (int j = 0; j < NDIM / (WN * 8); j++) {
            int col = wn * 64 + j * 8 + (lane & 3) * 2;
            if (row0 < M)
                *(__half2*)&Cout[(size_t)row0 * NDIM + col] =
                    __floats2half2_rn(acc[im][j][0], acc[im][j][1]);
            if (row1 < M)
                *(__half2*)&Cout[(size_t)row1 * NDIM + col] =
                    __floats2half2_rn(acc[im][j][2], acc[im][j][3]);
        }
    }
}

// ---------------------------------------------------------------------------
// Gather-reduce aggregation, 128 fp16 channels: one warp per dst node.
__global__ __launch_bounds__(256)
void agg128(const __half* __restrict__ hs, const float* __restrict__ bias,
            float* __restrict__ out, int n) {
    int warp = (blockIdx.x * blockDim.x + threadIdx.x) >> 5;
    int lane = threadIdx.x & 31;
    if (warp >= n) return;
    const int node = warp;
    const float dnode = g_dis[node];

    float4 acc;
    {
        uint2 r = *(const uint2*)&hs[(size_t)node * C1 + lane * 4];
        float2 f0 = __half22float2(*(__half2*)&r.x);
        float2 f1 = __half22float2(*(__half2*)&r.y);
        acc = make_float4(f0.x * dnode, f0.y * dnode, f1.x * dnode, f1.y * dnode);
    }
    int e   = g_rowstart[node];
    int cnt = g_deg[node];

    while (cnt > 0) {
        int take = min(cnt, 32);
        int2 sd = make_int2(0, 0);
        if (lane < take) sd = g_csr2[e + lane];
        int k = 0;
        for (; k + 8 <= take; k += 8) {
            uint2 r[8]; float dq[8];
#pragma unroll
            for (int q = 0; q < 8; q++) {
                int sq = __shfl_sync(0xffffffffu, sd.x, k + q);
                dq[q]  = __int_as_float(__shfl_sync(0xffffffffu, sd.y, k + q));
                r[q] = *(const uint2*)&hs[(size_t)sq * C1 + lane * 4];
            }
#pragma unroll
            for (int q = 0; q < 8; q++) {
                float2 f0 = __half22float2(*(__half2*)&r[q].x);
                float2 f1 = __half22float2(*(__half2*)&r[q].y);
                acc.x = fmaf(f0.x, dq[q], acc.x);
                acc.y = fmaf(f0.y, dq[q], acc.y);
                acc.z = fmaf(f1.x, dq[q], acc.z);
                acc.w = fmaf(f1.y, dq[q], acc.w);
            }
        }
        for (; k < take; k++) {
            int sk = __shfl_sync(0xffffffffu, sd.x, k);
            float dk = __int_as_float(__shfl_sync(0xffffffffu, sd.y, k));
            uint2 r = *(const uint2*)&hs[(size_t)sk * C1 + lane * 4];
            float2 f0 = __half22float2(*(__half2*)&r.x);
            float2 f1 = __half22float2(*(__half2*)&r.y);
            acc.x = fmaf(f0.x, dk, acc.x);
            acc.y = fmaf(f0.y, dk, acc.y);
            acc.z = fmaf(f1.x, dk, acc.z);
            acc.w = fmaf(f1.y, dk, acc.w);
        }
        e += take; cnt -= take;
    }

    float4 bb = ((const float4*)bias)[lane];
    float4 r;
    r.x = fmaxf(fmaf(dnode, acc.x, bb.x), 0.0f);
    r.y = fmaxf(fmaf(dnode, acc.y, bb.y), 0.0f);
    r.z = fmaxf(fmaf(dnode, acc.z, bb.z), 0.0f);
    r.w = fmaxf(fmaf(dnode, acc.w, bb.w), 0.0f);
    *(float4*)&out[(size_t)node * C1 + lane * 4] = r;
}

// 64-ch fp16 aggregation: one warp per node, each lane owns 2 channels (half2).
__global__ __launch_bounds__(256)
void agg64(const __half* __restrict__ hs, const float* __restrict__ bias,
           float* __restrict__ out, int n) {
    int warp = (blockIdx.x * blockDim.x + threadIdx.x) >> 5;
    int lane = threadIdx.x & 31;
    if (warp >= n) return;
    const int node = warp;
    const float dnode = g_dis[node];

    float2 acc;
    {
        uint32_t r = *(const uint32_t*)&hs[(size_t)node * C2 + lane * 2];
        float2 f = __half22float2(*(__half2*)&r);
        acc = make_float2(f.x * dnode, f.y * dnode);
    }
    int e   = g_rowstart[node];
    int cnt = g_deg[node];

    while (cnt > 0) {
        int take = min(cnt, 32);
        int2 sd = make_int2(0, 0);
        if (lane < take) sd = g_csr2[e + lane];
        int k = 0;
        for (; k + 8 <= take; k += 8) {
            uint32_t r[8]; float dq[8];
#pragma unroll
            for (int q = 0; q < 8; q++) {
                int sq = __shfl_sync(0xffffffffu, sd.x, k + q);
                dq[q]  = __int_as_float(__shfl_sync(0xffffffffu, sd.y, k + q));
                r[q] = *(const uint32_t*)&hs[(size_t)sq * C2 + lane * 2];
            }
#pragma unroll
            for (int q = 0; q < 8; q++) {
                float2 f = __half22float2(*(__half2*)&r[q]);
                acc.x = fmaf(f.x, dq[q], acc.x);
                acc.y = fmaf(f.y, dq[q], acc.y);
            }
        }
        for (; k < take; k++) {
            int sk = __shfl_sync(0xffffffffu, sd.x, k);
            float dk = __int_as_float(__shfl_sync(0xffffffffu, sd.y, k));
            uint32_t r = *(const uint32_t*)&hs[(size_t)sk * C2 + lane * 2];
            float2 f = __half22float2(*(__half2*)&r);
            acc.x = fmaf(f.x, dk, acc.x);
            acc.y = fmaf(f.y, dk, acc.y);
        }
        e += take; cnt -= take;
    }

    float2 bb = ((const float2*)bias)[lane];
    float2 r;
    r.x = fmaxf(fmaf(dnode, acc.x, bb.x), 0.0f);
    r.y = fmaxf(fmaf(dnode, acc.y, bb.y), 0.0f);
    *(float2*)&out[(size_t)node * C2 + lane * 2] = r;
}

// ---------------------------------------------------------------------------
extern "C" void kernel_launch(void* const* d_in, const int* in_sizes, int n_in,
                              void* d_out, int out_size) {
    const float* x  = (const float*)d_in[0];
    const int*   ei = (const int*)d_in[1];
    const float* W1 = (const float*)d_in[2];
    const float* b1 = (const float*)d_in[3];
    const float* W2 = (const float*)d_in[4];
    const float* b2 = (const float*)d_in[5];
    float* out = (float*)d_out;

    const int E = in_sizes[1] / 2;
    const int N = in_sizes[0] / IN_CH;
    const int* src = ei;
    const int* dst = ei + E;

    __half *h1, *h2;
    float *x2;
    uint4 *w1h, *w1l, *w2h, *w2l;
    cudaGetSymbolAddress((void**)&h1,  g_h1);
    cudaGetSymbolAddress((void**)&x2,  g_x2);
    cudaGetSymbolAddress((void**)&h2,  g_h2);
    cudaGetSymbolAddress((void**)&w1h, g_W1hi);
    cudaGetSymbolAddress((void**)&w1l, g_W1lo);
    cudaGetSymbolAddress((void**)&w2h, g_W2hi);
    cudaGetSymbolAddress((void**)&w2l, g_W2lo);

    constexpr int SMEM1 = 2 * 128 * 128 + 2 * 128 * 128;  // 65536
    constexpr int SMEM2 = 2 * 256 * 128 + 2 * 64 * 128;   // 81920
    cudaFuncSetAttribute(gemm_mma<128, 128, 256, 4, 2>,
                         cudaFuncAttributeMaxDynamicSharedMemorySize, SMEM1);
    cudaFuncSetAttribute(gemm_mma<256, 64, 128, 8, 1>,
                         cudaFuncAttributeMaxDynamicSharedMemorySize, SMEM2);

    // Lazily-created side stream + fork/join events (first call is uncaptured).
    static cudaStream_t s_side = nullptr;
    static cudaEvent_t  ev_fork = nullptr, ev_chain = nullptr;
    if (!s_side) {
        cudaStreamCreateWithFlags(&s_side, cudaStreamNonBlocking);
        cudaEventCreateWithFlags(&ev_fork,  cudaEventDisableTiming);
        cudaEventCreateWithFlags(&ev_chain, cudaEventDisableTiming);
    }

    // Fork immediately: side builds CSR chain, main builds W images + gemm1.
    cudaEventRecord(ev_fork, 0);
    cudaStreamWaitEvent(s_side, ev_fork, 0);

    // --- side: zero_deg -> deg -> scanA -> scanC -> fill_csr ---
    zero_deg<<<(N + 255) / 256, 256, 0, s_side>>>(N);
    deg_kernel<<<((E + 3) / 4 + 255) / 256, 256, 0, s_side>>>(dst, E);
    int nb = (N + 511) / 512;
    scanA<<<nb, 512, 0, s_side>>>(N);
    scanC<<<(N + 255) / 256, 256, 0, s_side>>>(N, nb);
    fill_csr<<<((E + 3) / 4 + 255) / 256, 256, 0, s_side>>>(src, dst, E);
    cudaEventRecord(ev_chain, s_side);

    // --- main: W images, then gemm1 (needs only W1 images + x) ---
    wprep_kernel<<<(IN_CH * C1 + 255) / 256, 256>>>(W1, W2);
    gemm_mma<128, 128, 256, 4, 2><<<(N + 127) / 128, 256, SMEM1>>>(x, w1h, w1l, h1, N);

    // Join: aggregation needs both gemm1 (stream order) and the CSR chain.
    cudaStreamWaitEvent(0, ev_chain, 0);
    agg128<<<(N * 32 + 255) / 256, 256>>>(h1, b1, x2, N);

    // ---- layer 2 (serial on main — proven fastest topology) ----
    gemm_mma<256, 64, 128, 8, 1><<<(N + 255) / 256, 256, SMEM2>>>(x2, w2h, w2l, h2, N);
    agg64<<<(N * 32 + 255) / 256, 256>>>(h2, b2, out, N);
}

// round 13
// speedup vs baseline: 1.1734x; 1.0702x over previous
#include <cuda_runtime.h>
#include <cuda_bf16.h>
#include <cuda_fp16.h>
#include <cstdint>

// Problem constants (fixed by the dataset)
#define NN_MAX   50000
#define EDGE_MAX 800000
#define IN_CH    256
#define C1       128
#define C2       64

// -------- scratch (no allocations allowed -> __device__ globals) -----------
__device__ int    g_deg     [NN_MAX];
__device__ int    g_prefix  [NN_MAX];
__device__ int    g_bsum    [256];
__device__ int    g_rowstart[NN_MAX];
__device__ int    g_cursor  [NN_MAX];
__device__ int2   g_csr2    [EDGE_MAX];      // (src, dis[src] bits) grouped by dst
__device__ float  g_dis     [NN_MAX];
__device__ __half g_h1      [NN_MAX * C1];   // x@W1 (raw, fp16)
__device__ __half g_x2      [NN_MAX * C1];   // relu output of layer 1 (fp16)
__device__ __half g_h2      [NN_MAX * C2];   // x2@W2 (raw, fp16)
// Pre-swizzled (SW128) bf16 hi/lo images of W^T, layout [kchunk][n][k64], 128B rows.
__device__ uint4 g_W1hi[4096], g_W1lo[4096];   // 4 chunks x 128n x 128B
__device__ uint4 g_W2hi[1024], g_W2lo[1024];   // 2 chunks x  64n x 128B

#define SW128(o) ((o) ^ (((o) >> 3) & 0x70))

__device__ __forceinline__ uint32_t smem_u32(const void* p) {
    uint32_t a;
    asm("{ .reg .u64 t; cvta.to.shared.u64 t, %1; cvt.u32.u64 %0, t; }" : "=r"(a) : "l"(p));
    return a;
}
__device__ __forceinline__ void ldsm_x4(uint32_t* r, uint32_t addr) {
    asm volatile("ldmatrix.sync.aligned.m8n8.x4.shared.b16 {%0,%1,%2,%3}, [%4];"
                 : "=r"(r[0]), "=r"(r[1]), "=r"(r[2]), "=r"(r[3]) : "r"(addr));
}
__device__ __forceinline__ void mma_bf16(float* d, const uint32_t* a,
                                         uint32_t b0, uint32_t b1) {
    asm volatile(
        "mma.sync.aligned.m16n8k16.row.col.f32.bf16.bf16.f32 "
        "{%0,%1,%2,%3}, {%4,%5,%6,%7}, {%8,%9}, {%0,%1,%2,%3};"
        : "+f"(d[0]), "+f"(d[1]), "+f"(d[2]), "+f"(d[3])
        : "r"(a[0]), "r"(a[1]), "r"(a[2]), "r"(a[3]), "r"(b0), "r"(b1));
}

// ---------------------------------------------------------------------------
// Fused prep: zero g_deg + build swizzled bf16 hi/lo weight images. (R9-proven)
__global__ void prep_kernel(const float* __restrict__ W1, const float* __restrict__ W2, int n) {
    int idx = blockIdx.x * blockDim.x + threadIdx.x;
    if (idx < n) g_deg[idx] = 0;
    if (idx < IN_CH * C1) {
        int k = idx / C1, nn = idx % C1;
        float v = W1[k * C1 + nn];
        __nv_bfloat16 h = __float2bfloat16_rn(v);
        __nv_bfloat16 l = __float2bfloat16_rn(v - __bfloat162float(h));
        int c = k >> 6, kk = k & 63;
        int off = c * 16384 + SW128(nn * 128 + kk * 2);
        *(__nv_bfloat16*)((char*)g_W1hi + off) = h;
        *(__nv_bfloat16*)((char*)g_W1lo + off) = l;
        if (idx < C1 * C2) {
            int k2 = idx / C2, n2 = idx % C2;
            float v2 = W2[k2 * C2 + n2];
            __nv_bfloat16 h2 = __float2bfloat16_rn(v2);
            __nv_bfloat16 l2 = __float2bfloat16_rn(v2 - __bfloat162float(h2));
            int c2 = k2 >> 6, kk2 = k2 & 63;
            int off2 = c2 * 8192 + SW128(n2 * 128 + kk2 * 2);
            *(__nv_bfloat16*)((char*)g_W2hi + off2) = h2;
            *(__nv_bfloat16*)((char*)g_W2lo + off2) = l2;
        }
    }
}

// Degree count: 4 edges per thread (int4 load) for MLP.
__global__ void deg_kernel(const int* __restrict__ dst, int E) {
    int base = (blockIdx.x * blockDim.x + threadIdx.x) * 4;
    if (base + 3 < E) {
        int4 d = *(const int4*)&dst[base];
        atomicAdd(&g_deg[d.x], 1);
        atomicAdd(&g_deg[d.y], 1);
        atomicAdd(&g_deg[d.z], 1);
        atomicAdd(&g_deg[d.w], 1);
    } else {
        for (int e = base; e < E; e++) atomicAdd(&g_deg[dst[e]], 1);
    }
}

// Parallel scan phase A: per-block exclusive prefix + block sums.
__global__ __launch_bounds__(512) void scanA(int n) {
    __shared__ int s[512];
    int t = threadIdx.x;
    int i = blockIdx.x * 512 + t;
    int v = (i < n) ? g_deg[i] : 0;
    s[t] = v; __syncthreads();
    for (int off = 1; off < 512; off <<= 1) {
        int u = (t >= off) ? s[t - off] : 0;
        __syncthreads(); s[t] += u; __syncthreads();
    }
    if (i < n) g_prefix[i] = s[t] - v;
    if (t == 511) g_bsum[blockIdx.x] = s[511];
}
// Phase B+C fused: every block redundantly scans the <=256 block sums in smem.
__global__ __launch_bounds__(256) void scanC(int n, int nb) {
    __shared__ int sb_[256];
    int t = threadIdx.x;
    int v = (t < nb) ? g_bsum[t] : 0;
    sb_[t] = v; __syncthreads();
    for (int off = 1; off < 256; off <<= 1) {
        int u = (t >= off) ? sb_[t - off] : 0;
        __syncthreads(); sb_[t] += u; __syncthreads();
    }
    if (t < nb) sb_[t] -= v;
    __syncthreads();
    int i = blockIdx.x * 256 + t;
    if (i >= n) return;
    int base = sb_[i >> 9] + g_prefix[i];
    g_rowstart[i] = base;
    g_cursor[i]   = base;
    g_dis[i]      = rsqrtf((float)g_deg[i] + 1.0f);
}

// CSR fill: packs (src, dis[src]) per edge; 4 edges per thread for MLP.
__global__ void fill_csr(const int* __restrict__ src, const int* __restrict__ dst, int E) {
    int base = (blockIdx.x * blockDim.x + threadIdx.x) * 4;
    if (base + 3 < E) {
        int4 d = *(const int4*)&dst[base];
        int4 s = *(const int4*)&src[base];
        float f0 = g_dis[s.x], f1 = g_dis[s.y], f2 = g_dis[s.z], f3 = g_dis[s.w];
        int p0 = atomicAdd(&g_cursor[d.x], 1);
        int p1 = atomicAdd(&g_cursor[d.y], 1);
        int p2 = atomicAdd(&g_cursor[d.z], 1);
        int p3 = atomicAdd(&g_cursor[d.w], 1);
        g_csr2[p0] = make_int2(s.x, __float_as_int(f0));
        g_csr2[p1] = make_int2(s.y, __float_as_int(f1));
        g_csr2[p2] = make_int2(s.z, __float_as_int(f2));
        g_csr2[p3] = make_int2(s.w, __float_as_int(f3));
    } else {
        for (int e = base; e < E; e++) {
            int s = src[e];
            int p = atomicAdd(&g_cursor[dst[e]], 1);
            g_csr2[p] = make_int2(s, __float_as_int(g_dis[s]));
        }
    }
}

// ---------------------------------------------------------------------------
// Warp-MMA split-bf16 GEMM: h[m][n] = half( sum_k A[m][k] * W[k][n] )
// AT = float (layer 1) or __half (layer 2; fp16 splits into bf16 hi+lo exactly).
template<int MTILE, int NDIM, int KDIM, int WM, int WN, typename AT>
__global__ __launch_bounds__(256) void gemm_mma(
    const AT* __restrict__ A, const uint4* __restrict__ Bhi,
    const uint4* __restrict__ Blo, __half* __restrict__ Cout, int M)
{
    constexpr int SA_HI = 0;
    constexpr int SA_LO = MTILE * 128;
    constexpr int SB_HI = 2 * MTILE * 128;
    constexpr int SB_LO = SB_HI + NDIM * 128;
    constexpr int NCH   = KDIM / 64;
    constexpr int BNV   = NDIM * 8;

    extern __shared__ char smem[];
    const uint32_t sb = smem_u32(smem);
    const int tid  = threadIdx.x;
    const int wid  = tid >> 5, lane = tid & 31;
    const int wm   = wid / WN, wn = wid % WN;
    const int m0   = blockIdx.x * MTILE;

    const int row_l  = lane & 15;
    const int colsel = (lane >> 4) * 8;

    float acc[2][NDIM / 8][4];
#pragma unroll
    for (int i = 0; i < 2; i++)
#pragma unroll
        for (int j = 0; j < NDIM / 8; j++)
#pragma unroll
            for (int q = 0; q < 4; q++) acc[i][j][q] = 0.0f;

    for (int c = 0; c < NCH; c++) {
        for (int i = tid; i < MTILE * 16; i += 256) {
            int m = i >> 4, kk = (i & 15) * 4;
            int gm = m0 + m;
            float4 v = make_float4(0.f, 0.f, 0.f, 0.f);
            if (gm < M) {
                if constexpr (sizeof(AT) == 4) {
                    v = *(const float4*)&A[(size_t)gm * KDIM + c * 64 + kk];
                } else {
                    uint2 hv = *(const uint2*)&A[(size_t)gm * KDIM + c * 64 + kk];
                    float2 a0 = __half22float2(*(__half2*)&hv.x);
                    float2 a1 = __half22float2(*(__half2*)&hv.y);
                    v = make_float4(a0.x, a0.y, a1.x, a1.y);
                }
            }
            __nv_bfloat16 h0 = __float2bfloat16_rn(v.x), h1 = __float2bfloat16_rn(v.y);
            __nv_bfloat16 h2 = __float2bfloat16_rn(v.z), h3 = __float2bfloat16_rn(v.w);
            __nv_bfloat16 l0 = __float2bfloat16_rn(v.x - __bfloat162float(h0));
            __nv_bfloat16 l1 = __float2bfloat16_rn(v.y - __bfloat162float(h1));
            __nv_bfloat16 l2 = __float2bfloat16_rn(v.z - __bfloat162float(h2));
            __nv_bfloat16 l3 = __float2bfloat16_rn(v.w - __bfloat162float(h3));
            uint32_t hA = ((uint32_t)__bfloat16_as_ushort(h1) << 16) | __bfloat16_as_ushort(h0);
            uint32_t hB = ((uint32_t)__bfloat16_as_ushort(h3) << 16) | __bfloat16_as_ushort(h2);
            uint32_t lA = ((uint32_t)__bfloat16_as_ushort(l1) << 16) | __bfloat16_as_ushort(l0);
            uint32_t lB = ((uint32_t)__bfloat16_as_ushort(l3) << 16) | __bfloat16_as_ushort(l2);
            int off = SW128(m * 128 + kk * 2);
            *(uint2*)(smem + SA_HI + off) = make_uint2(hA, hB);
            *(uint2*)(smem + SA_LO + off) = make_uint2(lA, lB);
        }
        {
            uint4* bh = (uint4*)(smem + SB_HI);
            uint4* bl = (uint4*)(smem + SB_LO);
            const uint4* gh = Bhi + (size_t)c * BNV;
            const uint4* gl = Blo + (size_t)c * BNV;
            for (int i = tid; i < BNV; i += 256) { bh[i] = gh[i]; bl[i] = gl[i]; }
        }
        __syncthreads();

#pragma unroll
        for (int k16 = 0; k16 < 4; k16++) {
            const int kb = k16 * 16;
            uint32_t ah[2][4], al[2][4];
#pragma unroll
            for (int im = 0; im < 2; im++) {
                int aoff = SW128((wm * 32 + im * 16 + row_l) * 128 + (kb + colsel) * 2);
                ldsm_x4(ah[im], sb + SA_HI + aoff);
                ldsm_x4(al[im], sb + SA_LO + aoff);
            }
#pragma unroll
            for (int j2 = 0; j2 < NDIM / (WN * 16); j2++) {
                int boff = SW128((wn * 64 + j2 * 16 + row_l) * 128 + (kb + colsel) * 2);
                uint32_t bh[4], bl[4];
                ldsm_x4(bh, sb + SB_HI + boff);
                ldsm_x4(bl, sb + SB_LO + boff);
#pragma unroll
                for (int im = 0; im < 2; im++) {
                    float* d0 = acc[im][2 * j2];
                    float* d1 = acc[im][2 * j2 + 1];
                    mma_bf16(d0, ah[im], bh[0], bh[2]);
                    mma_bf16(d0, ah[im], bl[0], bl[2]);
                    mma_bf16(d0, al[im], bh[0], bh[2]);
                    mma_bf16(d1, ah[im], bh[1], bh[3]);
                    mma_bf16(d1, ah[im], bl[1], bl[3]);
                    mma_bf16(d1, al[im], bh[1], bh[3]);
                }
            }
        }
        __syncthreads();
    }

#pragma unroll
    for (int im = 0; im < 2; im++) {
        int row0 = m0 + wm * 32 + im * 16 + (lane >> 2);
        int row1 = row0 + 8;
#pragma unroll
        for (int j = 0; j < NDIM / (WN * 8); j++) {
            int col = wn * 64 + j * 8 + (lane & 3) * 2;
            if (row0 < M)
                *(__half2*)&Cout[(size_t)row0 * NDIM + col] =
                    __floats2half2_rn(acc[im][j][0], acc[im][j][1]);
            if (row1 < M)
                *(__half2*)&Cout[(size_t)row1 * NDIM + col] =
                    __floats2half2_rn(acc[im][j][2], acc[im][j][3]);
        }
    }
}

// ---------------------------------------------------------------------------
// Gather-reduce aggregation, 128 fp16 channels: one warp per dst node.
// acc = h[node]*dis[node] + sum h[src]*dis[src];  out(fp16) = relu(dis*acc + b)
__global__ __launch_bounds__(256)
void agg128(const __half* __restrict__ hs, const float* __restrict__ bias,
            __half* __restrict__ out, int n) {
    int warp = (blockIdx.x * blockDim.x + threadIdx.x) >> 5;
    int lane = threadIdx.x & 31;
    if (warp >= n) return;
    const int node = warp;
    const float dnode = g_dis[node];

    float4 acc;
    {
        uint2 r = *(const uint2*)&hs[(size_t)node * C1 + lane * 4];
        float2 f0 = __half22float2(*(__half2*)&r.x);
        float2 f1 = __half22float2(*(__half2*)&r.y);
        acc = make_float4(f0.x * dnode, f0.y * dnode, f1.x * dnode, f1.y * dnode);
    }
    int e   = g_rowstart[node];
    int cnt = g_deg[node];

    while (cnt > 0) {
        int take = min(cnt, 32);
        int2 sd = make_int2(0, 0);
        if (lane < take) sd = g_csr2[e + lane];
        int k = 0;
        for (; k + 8 <= take; k += 8) {
            uint2 r[8]; float dq[8];
#pragma unroll
            for (int q = 0; q < 8; q++) {
                int sq = __shfl_sync(0xffffffffu, sd.x, k + q);
                dq[q]  = __int_as_float(__shfl_sync(0xffffffffu, sd.y, k + q));
                r[q] = *(const uint2*)&hs[(size_t)sq * C1 + lane * 4];
            }
#pragma unroll
            for (int q = 0; q < 8; q++) {
                float2 f0 = __half22float2(*(__half2*)&r[q].x);
                float2 f1 = __half22float2(*(__half2*)&r[q].y);
                acc.x = fmaf(f0.x, dq[q], acc.x);
                acc.y = fmaf(f0.y, dq[q], acc.y);
                acc.z = fmaf(f1.x, dq[q], acc.z);
                acc.w = fmaf(f1.y, dq[q], acc.w);
            }
        }
        for (; k < take; k++) {
            int sk = __shfl_sync(0xffffffffu, sd.x, k);
            float dk = __int_as_float(__shfl_sync(0xffffffffu, sd.y, k));
            uint2 r = *(const uint2*)&hs[(size_t)sk * C1 + lane * 4];
            float2 f0 = __half22float2(*(__half2*)&r.x);
            float2 f1 = __half22float2(*(__half2*)&r.y);
            acc.x = fmaf(f0.x, dk, acc.x);
            acc.y = fmaf(f0.y, dk, acc.y);
            acc.z = fmaf(f1.x, dk, acc.z);
            acc.w = fmaf(f1.y, dk, acc.w);
        }
        e += take; cnt -= take;
    }

    float4 bb = ((const float4*)bias)[lane];
    float rx = fmaxf(fmaf(dnode, acc.x, bb.x), 0.0f);
    float ry = fmaxf(fmaf(dnode, acc.y, bb.y), 0.0f);
    float rz = fmaxf(fmaf(dnode, acc.z, bb.z), 0.0f);
    float rw = fmaxf(fmaf(dnode, acc.w, bb.w), 0.0f);
    uint2 o;
    *(__half2*)&o.x = __floats2half2_rn(rx, ry);
    *(__half2*)&o.y = __floats2half2_rn(rz, rw);
    *(uint2*)&out[(size_t)node * C1 + lane * 4] = o;
}

// 64-ch fp16 aggregation: one warp per node, each lane owns 2 channels (half2).
__global__ __launch_bounds__(256)
void agg64(const __half* __restrict__ hs, const float* __restrict__ bias,
           float* __restrict__ out, int n) {
    int warp = (blockIdx.x * blockDim.x + threadIdx.x) >> 5;
    int lane = threadIdx.x & 31;
    if (warp >= n) return;
    const int node = warp;
    const float dnode = g_dis[node];

    float2 acc;
    {
        uint32_t r = *(const uint32_t*)&hs[(size_t)node * C2 + lane * 2];
        float2 f = __half22float2(*(__half2*)&r);
        acc = make_float2(f.x * dnode, f.y * dnode);
    }
    int e   = g_rowstart[node];
    int cnt = g_deg[node];

    while (cnt > 0) {
        int take = min(cnt, 32);
        int2 sd = make_int2(0, 0);
        if (lane < take) sd = g_csr2[e + lane];
        int k = 0;
        for (; k + 8 <= take; k += 8) {
            uint32_t r[8]; float dq[8];
#pragma unroll
            for (int q = 0; q < 8; q++) {
                int sq = __shfl_sync(0xffffffffu, sd.x, k + q);
                dq[q]  = __int_as_float(__shfl_sync(0xffffffffu, sd.y, k + q));
                r[q] = *(const uint32_t*)&hs[(size_t)sq * C2 + lane * 2];
            }
#pragma unroll
            for (int q = 0; q < 8; q++) {
                float2 f = __half22float2(*(__half2*)&r[q]);
                acc.x = fmaf(f.x, dq[q], acc.x);
                acc.y = fmaf(f.y, dq[q], acc.y);
            }
        }
        for (; k < take; k++) {
            int sk = __shfl_sync(0xffffffffu, sd.x, k);
            float dk = __int_as_float(__shfl_sync(0xffffffffu, sd.y, k));
            uint32_t r = *(const uint32_t*)&hs[(size_t)sk * C2 + lane * 2];
            float2 f = __half22float2(*(__half2*)&r);
            acc.x = fmaf(f.x, dk, acc.x);
            acc.y = fmaf(f.y, dk, acc.y);
        }
        e += take; cnt -= take;
    }

    float2 bb = ((const float2*)bias)[lane];
    float2 r;
    r.x = fmaxf(fmaf(dnode, acc.x, bb.x), 0.0f);
    r.y = fmaxf(fmaf(dnode, acc.y, bb.y), 0.0f);
    *(float2*)&out[(size_t)node * C2 + lane * 2] = r;
}

// ---------------------------------------------------------------------------
extern "C" void kernel_launch(void* const* d_in, const int* in_sizes, int n_in,
                              void* d_out, int out_size) {
    const float* x  = (const float*)d_in[0];
    const int*   ei = (const int*)d_in[1];
    const float* W1 = (const float*)d_in[2];
    const float* b1 = (const float*)d_in[3];
    const float* W2 = (const float*)d_in[4];
    const float* b2 = (const float*)d_in[5];
    float* out = (float*)d_out;

    const int E = in_sizes[1] / 2;
    const int N = in_sizes[0] / IN_CH;
    const int* src = ei;
    const int* dst = ei + E;

    __half *h1, *h2, *x2;
    uint4 *w1h, *w1l, *w2h, *w2l;
    cudaGetSymbolAddress((void**)&h1,  g_h1);
    cudaGetSymbolAddress((void**)&x2,  g_x2);
    cudaGetSymbolAddress((void**)&h2,  g_h2);
    cudaGetSymbolAddress((void**)&w1h, g_W1hi);
    cudaGetSymbolAddress((void**)&w1l, g_W1lo);
    cudaGetSymbolAddress((void**)&w2h, g_W2hi);
    cudaGetSymbolAddress((void**)&w2l, g_W2lo);

    constexpr int SMEM1 = 2 * 128 * 128 + 2 * 128 * 128;  // 65536
    constexpr int SMEM2 = 2 * 256 * 128 + 2 * 64 * 128;   // 81920
    cudaFuncSetAttribute(gemm_mma<128, 128, 256, 4, 2, float>,
                         cudaFuncAttributeMaxDynamicSharedMemorySize, SMEM1);
    cudaFuncSetAttribute(gemm_mma<256, 64, 128, 8, 1, __half>,
                         cudaFuncAttributeMaxDynamicSharedMemorySize, SMEM2);

    // Lazily-created side stream + fork/join events (first call is uncaptured).
    static cudaStream_t s_side = nullptr;
    static cudaEvent_t  ev_fork = nullptr, ev_chain = nullptr;
    if (!s_side) {
        cudaStreamCreateWithFlags(&s_side, cudaStreamNonBlocking);
        cudaEventCreateWithFlags(&ev_fork,  cudaEventDisableTiming);
        cudaEventCreateWithFlags(&ev_chain, cudaEventDisableTiming);
    }

    // prep: zero deg + weight images (R9-proven: fused, pre-fork, main stream)
    {
        int total = (N > IN_CH * C1) ? N : IN_CH * C1;
        prep_kernel<<<(total + 255) / 256, 256>>>(W1, W2, N);
    }

    // Fork: CSR-build chain on side stream, gemm1 on main stream (independent).
    cudaEventRecord(ev_fork, 0);
    cudaStreamWaitEvent(s_side, ev_fork, 0);

    deg_kernel<<<((E + 3) / 4 + 255) / 256, 256, 0, s_side>>>(dst, E);
    int nb = (N + 511) / 512;
    scanA<<<nb, 512, 0, s_side>>>(N);
    scanC<<<(N + 255) / 256, 256, 0, s_side>>>(N, nb);
    fill_csr<<<((E + 3) / 4 + 255) / 256, 256, 0, s_side>>>(src, dst, E);
    cudaEventRecord(ev_chain, s_side);

    // ---- layer 1 GEMM (no dis dependency) ----
    gemm_mma<128, 128, 256, 4, 2, float><<<(N + 127) / 128, 256, SMEM1>>>(x, w1h, w1l, h1, N);

    // Join: aggregation needs both gemm1 (stream order) and the CSR chain.
    cudaStreamWaitEvent(0, ev_chain, 0);
    agg128<<<(N * 32 + 255) / 256, 256>>>(h1, b1, x2, N);

    // ---- layer 2 (serial on main — proven fastest topology) ----
    gemm_mma<256, 64, 128, 8, 1, __half><<<(N + 255) / 256, 256, SMEM2>>>(x2, w2h, w2l, h2, N);
    agg64<<<(N * 32 + 255) / 256, 256>>>(h2, b2, out, N);
}

// round 15
// speedup vs baseline: 1.2566x; 1.0709x over previous
#include <cuda_runtime.h>
#include <cuda_bf16.h>
#include <cuda_fp16.h>
#include <cstdint>

// Problem constants (fixed by the dataset)
#define NN_MAX   50000
#define EDGE_MAX 800000
#define IN_CH    256
#define C1       128
#define C2       64

// -------- scratch (no allocations allowed -> __device__ globals) -----------
__device__ int    g_deg     [NN_MAX];
__device__ int    g_prefix  [NN_MAX];
__device__ int    g_bsum    [256];
__device__ int    g_rowstart[NN_MAX];
__device__ int    g_cursor  [NN_MAX];
__device__ int2   g_csr2    [EDGE_MAX];      // (src, dis[src] bits) grouped by dst
__device__ float  g_dis     [NN_MAX];
__device__ __half g_h1      [NN_MAX * C1];   // x@W1 (raw, fp16)
__device__ __half g_x2      [NN_MAX * C1];   // relu output of layer 1 (fp16)
__device__ __half g_h2      [NN_MAX * C2];   // x2@W2 (raw, fp16)
// Pre-swizzled (SW128) bf16 hi/lo images of W^T, layout [kchunk][n][k64], 128B rows.
__device__ uint4 g_W1hi[4096], g_W1lo[4096];   // 4 chunks x 128n x 128B
__device__ uint4 g_W2hi[1024], g_W2lo[1024];   // 2 chunks x  64n x 128B

#define SW128(o) ((o) ^ (((o) >> 3) & 0x70))

__device__ __forceinline__ uint32_t smem_u32(const void* p) {
    uint32_t a;
    asm("{ .reg .u64 t; cvta.to.shared.u64 t, %1; cvt.u32.u64 %0, t; }" : "=r"(a) : "l"(p));
    return a;
}
__device__ __forceinline__ void ldsm_x4(uint32_t* r, uint32_t addr) {
    asm volatile("ldmatrix.sync.aligned.m8n8.x4.shared.b16 {%0,%1,%2,%3}, [%4];"
                 : "=r"(r[0]), "=r"(r[1]), "=r"(r[2]), "=r"(r[3]) : "r"(addr));
}
__device__ __forceinline__ void mma_bf16(float* d, const uint32_t* a,
                                         uint32_t b0, uint32_t b1) {
    asm volatile(
        "mma.sync.aligned.m16n8k16.row.col.f32.bf16.bf16.f32 "
        "{%0,%1,%2,%3}, {%4,%5,%6,%7}, {%8,%9}, {%0,%1,%2,%3};"
        : "+f"(d[0]), "+f"(d[1]), "+f"(d[2]), "+f"(d[3])
        : "r"(a[0]), "r"(a[1]), "r"(a[2]), "r"(a[3]), "r"(b0), "r"(b1));
}
__device__ __forceinline__ void cp_async16(uint32_t saddr, const void* gaddr, int src_size) {
    asm volatile("cp.async.cg.shared.global [%0], [%1], 16, %2;"
                 :: "r"(saddr), "l"(gaddr), "r"(src_size) : "memory");
}
#define CP_COMMIT() asm volatile("cp.async.commit_group;" ::: "memory")
#define CP_WAIT0()  asm volatile("cp.async.wait_group 0;" ::: "memory")

// ---------------------------------------------------------------------------
// Fused prep: zero g_deg + build swizzled bf16 hi/lo weight images. (R9-proven)
__global__ void prep_kernel(const float* __restrict__ W1, const float* __restrict__ W2, int n) {
    int idx = blockIdx.x * blockDim.x + threadIdx.x;
    if (idx < n) g_deg[idx] = 0;
    if (idx < IN_CH * C1) {
        int k = idx / C1, nn = idx % C1;
        float v = W1[k * C1 + nn];
        __nv_bfloat16 h = __float2bfloat16_rn(v);
        __nv_bfloat16 l = __float2bfloat16_rn(v - __bfloat162float(h));
        int c = k >> 6, kk = k & 63;
        int off = c * 16384 + SW128(nn * 128 + kk * 2);
        *(__nv_bfloat16*)((char*)g_W1hi + off) = h;
        *(__nv_bfloat16*)((char*)g_W1lo + off) = l;
        if (idx < C1 * C2) {
            int k2 = idx / C2, n2 = idx % C2;
            float v2 = W2[k2 * C2 + n2];
            __nv_bfloat16 h2 = __float2bfloat16_rn(v2);
            __nv_bfloat16 l2 = __float2bfloat16_rn(v2 - __bfloat162float(h2));
            int c2 = k2 >> 6, kk2 = k2 & 63;
            int off2 = c2 * 8192 + SW128(n2 * 128 + kk2 * 2);
            *(__nv_bfloat16*)((char*)g_W2hi + off2) = h2;
            *(__nv_bfloat16*)((char*)g_W2lo + off2) = l2;
        }
    }
}

// Degree count: 4 edges per thread (int4 load) for MLP.
__global__ void deg_kernel(const int* __restrict__ dst, int E) {
    int base = (blockIdx.x * blockDim.x + threadIdx.x) * 4;
    if (base + 3 < E) {
        int4 d = *(const int4*)&dst[base];
        atomicAdd(&g_deg[d.x], 1);
        atomicAdd(&g_deg[d.y], 1);
        atomicAdd(&g_deg[d.z], 1);
        atomicAdd(&g_deg[d.w], 1);
    } else {
        for (int e = base; e < E; e++) atomicAdd(&g_deg[dst[e]], 1);
    }
}

// Parallel scan phase A: per-block exclusive prefix + block sums.
__global__ __launch_bounds__(512) void scanA(int n) {
    __shared__ int s[512];
    int t = threadIdx.x;
    int i = blockIdx.x * 512 + t;
    int v = (i < n) ? g_deg[i] : 0;
    s[t] = v; __syncthreads();
    for (int off = 1; off < 512; off <<= 1) {
        int u = (t >= off) ? s[t - off] : 0;
        __syncthreads(); s[t] += u; __syncthreads();
    }
    if (i < n) g_prefix[i] = s[t] - v;
    if (t == 511) g_bsum[blockIdx.x] = s[511];
}
// Phase B+C fused: every block redundantly scans the <=256 block sums in smem.
__global__ __launch_bounds__(256) void scanC(int n, int nb) {
    __shared__ int sb_[256];
    int t = threadIdx.x;
    int v = (t < nb) ? g_bsum[t] : 0;
    sb_[t] = v; __syncthreads();
    for (int off = 1; off < 256; off <<= 1) {
        int u = (t >= off) ? sb_[t - off] : 0;
        __syncthreads(); sb_[t] += u; __syncthreads();
    }
    if (t < nb) sb_[t] -= v;
    __syncthreads();
    int i = blockIdx.x * 256 + t;
    if (i >= n) return;
    int base = sb_[i >> 9] + g_prefix[i];
    g_rowstart[i] = base;
    g_cursor[i]   = base;
    g_dis[i]      = rsqrtf((float)g_deg[i] + 1.0f);
}

// CSR fill: packs (src, dis[src]) per edge; 4 edges per thread for MLP.
__global__ void fill_csr(const int* __restrict__ src, const int* __restrict__ dst, int E) {
    int base = (blockIdx.x * blockDim.x + threadIdx.x) * 4;
    if (base + 3 < E) {
        int4 d = *(const int4*)&dst[base];
        int4 s = *(const int4*)&src[base];
        float f0 = g_dis[s.x], f1 = g_dis[s.y], f2 = g_dis[s.z], f3 = g_dis[s.w];
        int p0 = atomicAdd(&g_cursor[d.x], 1);
        int p1 = atomicAdd(&g_cursor[d.y], 1);
        int p2 = atomicAdd(&g_cursor[d.z], 1);
        int p3 = atomicAdd(&g_cursor[d.w], 1);
        g_csr2[p0] = make_int2(s.x, __float_as_int(f0));
        g_csr2[p1] = make_int2(s.y, __float_as_int(f1));
        g_csr2[p2] = make_int2(s.z, __float_as_int(f2));
        g_csr2[p3] = make_int2(s.w, __float_as_int(f3));
    } else {
        for (int e = base; e < E; e++) {
            int s = src[e];
            int p = atomicAdd(&g_cursor[dst[e]], 1);
            g_csr2[p] = make_int2(s, __float_as_int(g_dis[s]));
        }
    }
}

// ---------------------------------------------------------------------------
// Warp-MMA split-bf16 GEMM with cp.async double-buffered A staging.
// h[m][n] = half( sum_k A[m][k] * W[k][n] );  AT = float or __half.
template<int MTILE, int NDIM, int KDIM, int WM, int WN, typename AT>
__global__ __launch_bounds__(256) void gemm_mma(
    const AT* __restrict__ A, const uint4* __restrict__ Bhi,
    const uint4* __restrict__ Blo, __half* __restrict__ Cout, int M)
{
    constexpr int SA_HI   = 0;
    constexpr int SA_LO   = MTILE * 128;
    constexpr int SB_HI   = 2 * MTILE * 128;
    constexpr int SB_LO   = SB_HI + NDIM * 128;
    constexpr int SM_RAW  = SB_LO + NDIM * 128;
    constexpr int ROW_B   = 64 * (int)sizeof(AT);     // raw row bytes
    constexpr int RAW_B   = MTILE * ROW_B;            // raw chunk bytes
    constexpr int GPR     = ROW_B / 16;               // 16B granules per row
    constexpr int NCH     = KDIM / 64;
    constexpr int BNV     = NDIM * 8;

    extern __shared__ char smem[];
    const uint32_t sb = smem_u32(smem);
    const int tid  = threadIdx.x;
    const int wid  = tid >> 5, lane = tid & 31;
    const int wm   = wid / WN, wn = wid % WN;
    const int m0   = blockIdx.x * MTILE;

    const int row_l  = lane & 15;
    const int colsel = (lane >> 4) * 8;

    float acc[2][NDIM / 8][4];
#pragma unroll
    for (int i = 0; i < 2; i++)
#pragma unroll
        for (int j = 0; j < NDIM / 8; j++)
#pragma unroll
            for (int q = 0; q < 4; q++) acc[i][j][q] = 0.0f;

    // Prefetch raw A chunk c into buffer buf via cp.async (zfill OOB rows).
    auto copy_chunk = [&](int c, int buf) {
        uint32_t raw = sb + SM_RAW + buf * RAW_B;
        for (int g = tid; g < MTILE * GPR; g += 256) {
            int r  = g / GPR;
            int cb = (g % GPR) * 16;
            int gm = m0 + r;
            const char* srcp = (const char*)&A[(size_t)(gm < M ? gm : 0) * KDIM + c * 64] + cb;
            int sz = (gm < M) ? 16 : 0;
            cp_async16(raw + r * ROW_B + cb, srcp, sz);
        }
        CP_COMMIT();
    };

    copy_chunk(0, 0);

    for (int c = 0; c < NCH; c++) {
        const int buf = c & 1;
        CP_WAIT0();
        __syncthreads();                   // raw[buf] fully visible to all threads
        if (c + 1 < NCH) copy_chunk(c + 1, (c + 1) & 1);   // overlaps convert+MMA

        // Convert raw A chunk (SMEM) -> hi/lo bf16 SW128 SMEM images.
        const char* rawp = smem + SM_RAW + buf * RAW_B;
        for (int i = tid; i < MTILE * 16; i += 256) {
            int m = i >> 4, kk = (i & 15) * 4;
            float4 v;
            if constexpr (sizeof(AT) == 4) {
                v = *(const float4*)(rawp + m * ROW_B + (i & 15) * 16);
            } else {
                uint2 hv = *(const uint2*)(rawp + m * ROW_B + (i & 15) * 8);
                float2 a0 = __half22float2(*(__half2*)&hv.x);
                float2 a1 = __half22float2(*(__half2*)&hv.y);
                v = make_float4(a0.x, a0.y, a1.x, a1.y);
            }
            __nv_bfloat16 h0 = __float2bfloat16_rn(v.x), h1 = __float2bfloat16_rn(v.y);
            __nv_bfloat16 h2 = __float2bfloat16_rn(v.z), h3 = __float2bfloat16_rn(v.w);
            __nv_bfloat16 l0 = __float2bfloat16_rn(v.x - __bfloat162float(h0));
            __nv_bfloat16 l1 = __float2bfloat16_rn(v.y - __bfloat162float(h1));
            __nv_bfloat16 l2 = __float2bfloat16_rn(v.z - __bfloat162float(h2));
            __nv_bfloat16 l3 = __float2bfloat16_rn(v.w - __bfloat162float(h3));
            uint32_t hA = ((uint32_t)__bfloat16_as_ushort(h1) << 16) | __bfloat16_as_ushort(h0);
            uint32_t hB = ((uint32_t)__bfloat16_as_ushort(h3) << 16) | __bfloat16_as_ushort(h2);
            uint32_t lA = ((uint32_t)__bfloat16_as_ushort(l1) << 16) | __bfloat16_as_ushort(l0);
            uint32_t lB = ((uint32_t)__bfloat16_as_ushort(l3) << 16) | __bfloat16_as_ushort(l2);
            int off = SW128(m * 128 + kk * 2);
            *(uint2*)(smem + SA_HI + off) = make_uint2(hA, hB);
            *(uint2*)(smem + SA_LO + off) = make_uint2(lA, lB);
        }
        // Stage B chunk (pre-swizzled images; L2-hot across CTAs).
        {
            uint4* bh = (uint4*)(smem + SB_HI);
            uint4* bl = (uint4*)(smem + SB_LO);
            const uint4* gh = Bhi + (size_t)c * BNV;
            const uint4* gl = Blo + (size_t)c * BNV;
            for (int i = tid; i < BNV; i += 256) { bh[i] = gh[i]; bl[i] = gl[i]; }
        }
        __syncthreads();

#pragma unroll
        for (int k16 = 0; k16 < 4; k16++) {
            const int kb = k16 * 16;
            uint32_t ah[2][4], al[2][4];
#pragma unroll
            for (int im = 0; im < 2; im++) {
                int aoff = SW128((wm * 32 + im * 16 + row_l) * 128 + (kb + colsel) * 2);
                ldsm_x4(ah[im], sb + SA_HI + aoff);
                ldsm_x4(al[im], sb + SA_LO + aoff);
            }
#pragma unroll
            for (int j2 = 0; j2 < NDIM / (WN * 16); j2++) {
                int boff = SW128((wn * 64 + j2 * 16 + row_l) * 128 + (kb + colsel) * 2);
                uint32_t bh[4], bl[4];
                ldsm_x4(bh, sb + SB_HI + boff);
                ldsm_x4(bl, sb + SB_LO + boff);
#pragma unroll
                for (int im = 0; im < 2; im++) {
                    float* d0 = acc[im][2 * j2];
                    float* d1 = acc[im][2 * j2 + 1];
                    mma_bf16(d0, ah[im], bh[0], bh[2]);
                    mma_bf16(d0, ah[im], bl[0], bl[2]);
                    mma_bf16(d0, al[im], bh[0], bh[2]);
                    mma_bf16(d1, ah[im], bh[1], bh[3]);
                    mma_bf16(d1, ah[im], bl[1], bl[3]);
                    mma_bf16(d1, al[im], bh[1], bh[3]);
                }
            }
        }
        __syncthreads();
    }

#pragma unroll
    for (int im = 0; im < 2; im++) {
        int row0 = m0 + wm * 32 + im * 16 + (lane >> 2);
        int row1 = row0 + 8;
#pragma unroll
        for (int j = 0; j < NDIM / (WN * 8); j++) {
            int col = wn * 64 + j * 8 + (lane & 3) * 2;
            if (row0 < M)
                *(__half2*)&Cout[(size_t)row0 * NDIM + col] =
                    __floats2half2_rn(acc[im][j][0], acc[im][j][1]);
            if (row1 < M)
                *(__half2*)&Cout[(size_t)row1 * NDIM + col] =
                    __floats2half2_rn(acc[im][j][2], acc[im][j][3]);
        }
    }
}

// ---------------------------------------------------------------------------
// Gather-reduce aggregation, 128 fp16 channels: one warp per dst node.
__global__ __launch_bounds__(256)
void agg128(const __half* __restrict__ hs, const float* __restrict__ bias,
            __half* __restrict__ out, int n) {
    int warp = (blockIdx.x * blockDim.x + threadIdx.x) >> 5;
    int lane = threadIdx.x & 31;
    if (warp >= n) return;
    const int node = warp;
    const float dnode = g_dis[node];

    float4 acc;
    {
        uint2 r = *(const uint2*)&hs[(size_t)node * C1 + lane * 4];
        float2 f0 = __half22float2(*(__half2*)&r.x);
        float2 f1 = __half22float2(*(__half2*)&r.y);
        acc = make_float4(f0.x * dnode, f0.y * dnode, f1.x * dnode, f1.y * dnode);
    }
    int e   = g_rowstart[node];
    int cnt = g_deg[node];

    while (cnt > 0) {
        int take = min(cnt, 32);
        int2 sd = make_int2(0, 0);
        if (lane < take) sd = g_csr2[e + lane];
        int k = 0;
        for (; k + 8 <= take; k += 8) {
            uint2 r[8]; float dq[8];
#pragma unroll
            for (int q = 0; q < 8; q++) {
                int sq = __shfl_sync(0xffffffffu, sd.x, k + q);
                dq[q]  = __int_as_float(__shfl_sync(0xffffffffu, sd.y, k + q));
                r[q] = *(const uint2*)&hs[(size_t)sq * C1 + lane * 4];
            }
#pragma unroll
            for (int q = 0; q < 8; q++) {
                float2 f0 = __half22float2(*(__half2*)&r[q].x);
                float2 f1 = __half22float2(*(__half2*)&r[q].y);
                acc.x = fmaf(f0.x, dq[q], acc.x);
                acc.y = fmaf(f0.y, dq[q], acc.y);
                acc.z = fmaf(f1.x, dq[q], acc.z);
                acc.w = fmaf(f1.y, dq[q], acc.w);
            }
        }
        for (; k < take; k++) {
            int sk = __shfl_sync(0xffffffffu, sd.x, k);
            float dk = __int_as_float(__shfl_sync(0xffffffffu, sd.y, k));
            uint2 r = *(const uint2*)&hs[(size_t)sk * C1 + lane * 4];
            float2 f0 = __half22float2(*(__half2*)&r.x);
            float2 f1 = __half22float2(*(__half2*)&r.y);
            acc.x = fmaf(f0.x, dk, acc.x);
            acc.y = fmaf(f0.y, dk, acc.y);
            acc.z = fmaf(f1.x, dk, acc.z);
            acc.w = fmaf(f1.y, dk, acc.w);
        }
        e += take; cnt -= take;
    }

    float4 bb = ((const float4*)bias)[lane];
    float rx = fmaxf(fmaf(dnode, acc.x, bb.x), 0.0f);
    float ry = fmaxf(fmaf(dnode, acc.y, bb.y), 0.0f);
    float rz = fmaxf(fmaf(dnode, acc.z, bb.z), 0.0f);
    float rw = fmaxf(fmaf(dnode, acc.w, bb.w), 0.0f);
    uint2 o;
    *(__half2*)&o.x = __floats2half2_rn(rx, ry);
    *(__half2*)&o.y = __floats2half2_rn(rz, rw);
    *(uint2*)&out[(size_t)node * C1 + lane * 4] = o;
}

// 64-ch fp16 aggregation: one warp per node, each lane owns 2 channels (half2).
__global__ __launch_bounds__(256)
void agg64(const __half* __restrict__ hs, const float* __restrict__ bias,
           float* __restrict__ out, int n) {
    int warp = (blockIdx.x * blockDim.x + threadIdx.x) >> 5;
    int lane = threadIdx.x & 31;
    if (warp >= n) return;
    const int node = warp;
    const float dnode = g_dis[node];

    float2 acc;
    {
        uint32_t r = *(const uint32_t*)&hs[(size_t)node * C2 + lane * 2];
        float2 f = __half22float2(*(__half2*)&r);
        acc = make_float2(f.x * dnode, f.y * dnode);
    }
    int e   = g_rowstart[node];
    int cnt = g_deg[node];

    while (cnt > 0) {
        int take = min(cnt, 32);
        int2 sd = make_int2(0, 0);
        if (lane < take) sd = g_csr2[e + lane];
        int k = 0;
        for (; k + 8 <= take; k += 8) {
            uint32_t r[8]; float dq[8];
#pragma unroll
            for (int q = 0; q < 8; q++) {
                int sq = __shfl_sync(0xffffffffu, sd.x, k + q);
                dq[q]  = __int_as_float(__shfl_sync(0xffffffffu, sd.y, k + q));
                r[q] = *(const uint32_t*)&hs[(size_t)sq * C2 + lane * 2];
            }
#pragma unroll
            for (int q = 0; q < 8; q++) {
                float2 f = __half22float2(*(__half2*)&r[q]);
                acc.x = fmaf(f.x, dq[q], acc.x);
                acc.y = fmaf(f.y, dq[q], acc.y);
            }
        }
        for (; k < take; k++) {
            int sk = __shfl_sync(0xffffffffu, sd.x, k);
            float dk = __int_as_float(__shfl_sync(0xffffffffu, sd.y, k));
            uint32_t r = *(const uint32_t*)&hs[(size_t)sk * C2 + lane * 2];
            float2 f = __half22float2(*(__half2*)&r);
            acc.x = fmaf(f.x, dk, acc.x);
            acc.y = fmaf(f.y, dk, acc.y);
        }
        e += take; cnt -= take;
    }

    float2 bb = ((const float2*)bias)[lane];
    float2 r;
    r.x = fmaxf(fmaf(dnode, acc.x, bb.x), 0.0f);
    r.y = fmaxf(fmaf(dnode, acc.y, bb.y), 0.0f);
    *(float2*)&out[(size_t)node * C2 + lane * 2] = r;
}

// ---------------------------------------------------------------------------
extern "C" void kernel_launch(void* const* d_in, const int* in_sizes, int n_in,
                              void* d_out, int out_size) {
    const float* x  = (const float*)d_in[0];
    const int*   ei = (const int*)d_in[1];
    const float* W1 = (const float*)d_in[2];
    const float* b1 = (const float*)d_in[3];
    const float* W2 = (const float*)d_in[4];
    const float* b2 = (const float*)d_in[5];
    float* out = (float*)d_out;

    const int E = in_sizes[1] / 2;
    const int N = in_sizes[0] / IN_CH;
    const int* src = ei;
    const int* dst = ei + E;

    __half *h1, *h2, *x2;
    uint4 *w1h, *w1l, *w2h, *w2l;
    cudaGetSymbolAddress((void**)&h1,  g_h1);
    cudaGetSymbolAddress((void**)&x2,  g_x2);
    cudaGetSymbolAddress((void**)&h2,  g_h2);
    cudaGetSymbolAddress((void**)&w1h, g_W1hi);
    cudaGetSymbolAddress((void**)&w1l, g_W1lo);
    cudaGetSymbolAddress((void**)&w2h, g_W2hi);
    cudaGetSymbolAddress((void**)&w2l, g_W2lo);

    // smem = A hi/lo + B hi/lo + 2 raw staging buffers
    constexpr int SMEM1 = 2 * 128 * 128 + 2 * 128 * 128 + 2 * 128 * 256;  // 131072
    constexpr int SMEM2 = 2 * 256 * 128 + 2 * 64 * 128 + 2 * 256 * 128;   // 147456
    cudaFuncSetAttribute(gemm_mma<128, 128, 256, 4, 2, float>,
                         cudaFuncAttributeMaxDynamicSharedMemorySize, SMEM1);
    cudaFuncSetAttribute(gemm_mma<256, 64, 128, 8, 1, __half>,
                         cudaFuncAttributeMaxDynamicSharedMemorySize, SMEM2);

    // Lazily-created side stream + fork/join events (first call is uncaptured).
    static cudaStream_t s_side = nullptr;
    static cudaEvent_t  ev_fork = nullptr, ev_chain = nullptr;
    if (!s_side) {
        cudaStreamCreateWithFlags(&s_side, cudaStreamNonBlocking);
        cudaEventCreateWithFlags(&ev_fork,  cudaEventDisableTiming);
        cudaEventCreateWithFlags(&ev_chain, cudaEventDisableTiming);
    }

    // prep: zero deg + weight images (R9-proven: fused, pre-fork, main stream)
    {
        int total = (N > IN_CH * C1) ? N : IN_CH * C1;
        prep_kernel<<<(total + 255) / 256, 256>>>(W1, W2, N);
    }

    // Fork: CSR-build chain on side stream, gemm1 on main stream (independent).
    cudaEventRecord(ev_fork, 0);
    cudaStreamWaitEvent(s_side, ev_fork, 0);

    deg_kernel<<<((E + 3) / 4 + 255) / 256, 256, 0, s_side>>>(dst, E);
    int nb = (N + 511) / 512;
    scanA<<<nb, 512, 0, s_side>>>(N);
    scanC<<<(N + 255) / 256, 256, 0, s_side>>>(N, nb);
    fill_csr<<<((E + 3) / 4 + 255) / 256, 256, 0, s_side>>>(src, dst, E);
    cudaEventRecord(ev_chain, s_side);

    // ---- layer 1 GEMM (no dis dependency) ----
    gemm_mma<128, 128, 256, 4, 2, float><<<(N + 127) / 128, 256, SMEM1>>>(x, w1h, w1l, h1, N);

    // Join: aggregation needs both gemm1 (stream order) and the CSR chain.
    cudaStreamWaitEvent(0, ev_chain, 0);
    agg128<<<(N * 32 + 255) / 256, 256>>>(h1, b1, x2, N);

    // ---- layer 2 (serial on main — proven fastest topology) ----
    gemm_mma<256, 64, 128, 8, 1, __half><<<(N + 255) / 256, 256, SMEM2>>>(x2, w2h, w2l, h2, N);
    agg64<<<(N * 32 + 255) / 256, 256>>>(h2, b2, out, N);
}